// round 4
// baseline (speedup 1.0000x reference)
#include <cuda_runtime.h>

// GaussianBlur2D: circular Gaussian blur, separable direct convolution.
// x: [8,1,2048,2048] fp32, sigma_: scalar fp32. sigma ~= 2.0 -> radius 16
// truncation (tail mass ~1e-15, far below the 1e-3 rel_err threshold).

#define BATCH  8
#define HDIM   2048
#define WDIM   2048
#define RAD    16
#define WIN    (8 + 2 * RAD)      // 40-float sliding window per thread
#define NPIX   (BATCH * HDIM * WDIM)

__device__ float g_wn[RAD + 1];           // normalized 1D weights
__device__ float g_tmp[NPIX];             // scratch between passes

// ---------------------------------------------------------------------------
// Compute normalized 1D Gaussian weights from the device-side sigma scalar.
// Normalization: 1D sum over the truncated support; squared across the two
// passes this matches the reference's 2D-sum normalization to ~2e-9 relative.
// ---------------------------------------------------------------------------
__global__ void gb_weights_kernel(const float* __restrict__ sigma_) {
    if (threadIdx.x == 0) {
        float s = fmaxf(sigma_[0], 0.0f) + 1e-6f;
        float inv2s2 = 1.0f / (2.0f * s * s);
        float w[RAD + 1];
        float sum = 0.0f;
        #pragma unroll
        for (int d = 0; d <= RAD; d++) {
            w[d] = expf(-(float)(d * d) * inv2s2);
            sum += (d == 0) ? w[d] : 2.0f * w[d];
        }
        float inv = 1.0f / sum;
        #pragma unroll
        for (int d = 0; d <= RAD; d++) g_wn[d] = w[d] * inv;
    }
}

// ---------------------------------------------------------------------------
// Horizontal pass: circular 1D conv along W (contiguous dim).
// One block per row (B*H = 16384 rows), 256 threads, 8 outputs per thread.
// Window loads are float4: start index 8t-16 is 4-aligned, and 4-float groups
// never straddle the wrap (2048 % 4 == 0), so (idx & 2047) per group is exact.
// ---------------------------------------------------------------------------
__global__ __launch_bounds__(256) void gb_hpass_kernel(
    const float* __restrict__ x, float* __restrict__ out)
{
    const int row = blockIdx.x;
    const float* __restrict__ src = x   + (size_t)row * WDIM;
    float*       __restrict__ dst = out + (size_t)row * WDIM;

    float wn[RAD + 1];
    #pragma unroll
    for (int d = 0; d <= RAD; d++) wn[d] = g_wn[d];

    const int j0 = threadIdx.x * 8;

    float win[WIN];
    #pragma unroll
    for (int g = 0; g < WIN / 4; g++) {
        int idx = (j0 - RAD + 4 * g) & (WDIM - 1);
        float4 v = *reinterpret_cast<const float4*>(src + idx);
        win[4 * g + 0] = v.x; win[4 * g + 1] = v.y;
        win[4 * g + 2] = v.z; win[4 * g + 3] = v.w;
    }

    float acc[8];
    #pragma unroll
    for (int k = 0; k < 8; k++) {
        float a = wn[0] * win[k + RAD];
        #pragma unroll
        for (int d = 1; d <= RAD; d++)
            a += wn[d] * (win[k + RAD - d] + win[k + RAD + d]);
        acc[k] = a;
    }

    float4* dst4 = reinterpret_cast<float4*>(dst + j0);
    dst4[0] = make_float4(acc[0], acc[1], acc[2], acc[3]);
    dst4[1] = make_float4(acc[4], acc[5], acc[6], acc[7]);
}

// ---------------------------------------------------------------------------
// Vertical pass: circular 1D conv along H. blockDim (32, 8): 32 contiguous x
// per warp -> every row access is one coalesced 128B transaction. Each thread
// produces 8 consecutive y outputs from a 40-row register window; the 16-row
// halos overlap neighboring thread tiles and hit L1/L2.
// ---------------------------------------------------------------------------
__global__ __launch_bounds__(256) void gb_vpass_kernel(
    const float* __restrict__ t, float* __restrict__ out)
{
    const int b    = blockIdx.z;
    const int xcol = blockIdx.x * 32 + threadIdx.x;
    const int y0   = (blockIdx.y * 8 + threadIdx.y) * 8;

    const float* __restrict__ src = t   + (size_t)b * HDIM * WDIM + xcol;
    float*       __restrict__ dst = out + (size_t)b * HDIM * WDIM + xcol;

    float wn[RAD + 1];
    #pragma unroll
    for (int d = 0; d <= RAD; d++) wn[d] = g_wn[d];

    float win[WIN];
    #pragma unroll
    for (int i = 0; i < WIN; i++) {
        int y = (y0 - RAD + i) & (HDIM - 1);
        win[i] = __ldg(src + (size_t)y * WDIM);
    }

    #pragma unroll
    for (int k = 0; k < 8; k++) {
        float a = wn[0] * win[k + RAD];
        #pragma unroll
        for (int d = 1; d <= RAD; d++)
            a += wn[d] * (win[k + RAD - d] + win[k + RAD + d]);
        dst[(size_t)(y0 + k) * WDIM] = a;
    }
}

// ---------------------------------------------------------------------------
extern "C" void kernel_launch(void* const* d_in, const int* in_sizes, int n_in,
                              void* d_out, int out_size)
{
    const float* x      = (const float*)d_in[0];
    const float* sigma_ = (const float*)d_in[1];
    float* out          = (float*)d_out;

    float* tmp;
    cudaGetSymbolAddress((void**)&tmp, g_tmp);

    gb_weights_kernel<<<1, 32>>>(sigma_);

    gb_hpass_kernel<<<BATCH * HDIM, 256>>>(x, tmp);

    dim3 vgrid(WDIM / 32, HDIM / 64, BATCH);
    dim3 vblock(32, 8);
    gb_vpass_kernel<<<vgrid, vblock>>>(tmp, out);
}